// round 2
// baseline (speedup 1.0000x reference)
#include <cuda_runtime.h>
#include <math.h>

#define MROWS 32768
#define RELUF 1
#define ACCF  2
#define RESF  4

/* scratch offsets in floats */
#define O_LN    0ul
#define O_QKV   4194304ul
#define O_R     29360128ul
#define O_TMP   46137344ul
#define O_XT    50331648ul
#define O_FEAT  54525952ul
#define O_FUS   104857600ul
#define O_GATES 113246208ul
#define O_P1    146800640ul
#define O_P2    155189248ul
#define O_WQKV  157286400ul
#define O_WCONV 158072832ul
#define O_WC    159252480ul
#define O_WAB   159776768ul
#define BUFSZ   159907840ul

__device__ __align__(256) float BUF[BUFSZ];

/* ---------------- weight prep ---------------- */
__global__ void prep_qkv(const float* __restrict__ Wq, const float* __restrict__ Wk,
                         const float* __restrict__ Wv, float* __restrict__ o)
{
    int n = blockIdx.x, l = blockIdx.y, k = threadIdx.x;
    float v;
    if (n < 128)      v = Wq[((long)l*128 + k)*128 + n];
    else if (n < 256) v = Wk[((long)l*128 + k)*128 + (n-128)];
    else              v = Wv[((long)l*128 + k)*512 + (n-256)];
    o[((long)l*768 + n)*128 + k] = v;
}
__global__ void prep_wc(const float* __restrict__ Ww, const float* __restrict__ Wa,
                        float* __restrict__ o)
{
    int i = blockIdx.x, l = blockIdx.y, n = threadIdx.x;
    float s = 0.f;
    for (int j = 0; j < 128; j++)
        s = fmaf(Ww[((long)l*512 + i)*128 + j], Wa[((long)l*256 + j)*128 + n], s);
    o[((long)l*128 + n)*512 + i] = s;
}
__global__ void prep_wab(const float* __restrict__ Wa, float* __restrict__ o)
{
    int i = blockIdx.x, l = blockIdx.y, n = threadIdx.x;
    o[((long)l*128 + n)*128 + i] = Wa[((long)l*256 + 128 + i)*128 + n];
}
__global__ void prep_conv(const float* __restrict__ cw, float* __restrict__ o)
{
    int t = blockIdx.x >> 7, oc = blockIdx.x & 127, l = blockIdx.y, c = threadIdx.x;
    o[(((long)l*9 + t)*128 + oc)*128 + c] = cw[(((long)l*128 + oc)*128 + c)*9 + t];
}
/* x (B,C,K) -> XT (B,K,C) */
__global__ void transpose_x(const float* __restrict__ x, float* __restrict__ xt)
{
    __shared__ float t[32][33];
    int b = blockIdx.z, k0 = blockIdx.x*32, c0 = blockIdx.y*32;
    int tx = threadIdx.x, ty = threadIdx.y;
    const float* xb = x + (long)b*128*512;
    #pragma unroll
    for (int i = 0; i < 32; i += 8) t[ty+i][tx] = xb[(long)(c0+ty+i)*512 + k0+tx];
    __syncthreads();
    float* xo = xt + (long)b*512*128;
    #pragma unroll
    for (int i = 0; i < 32; i += 8) xo[(long)(k0+ty+i)*128 + c0+tx] = t[tx][ty+i];
}

/* ---------------- layernorm (warp per row of 128) ---------------- */
__global__ __launch_bounds__(256) void ln_kernel(const float* __restrict__ in, int lda,
                                                 const float* __restrict__ g,
                                                 const float* __restrict__ bt,
                                                 float* __restrict__ out)
{
    int m = blockIdx.x*8 + (threadIdx.x >> 5);
    int lane = threadIdx.x & 31;
    float4 v = *(const float4*)(in + (long)m*lda + lane*4);
    float s = v.x+v.y+v.z+v.w, sq = v.x*v.x+v.y*v.y+v.z*v.z+v.w*v.w;
    #pragma unroll
    for (int o = 16; o; o >>= 1) {
        s  += __shfl_xor_sync(~0u, s,  o);
        sq += __shfl_xor_sync(~0u, sq, o);
    }
    float mu = s*(1.f/128.f), var = sq*(1.f/128.f) - mu*mu;
    float inv = rsqrtf(var + 1e-6f);
    float4 gg = *(const float4*)(g + lane*4), bb = *(const float4*)(bt + lane*4);
    float4 o4 = { (v.x-mu)*inv*gg.x+bb.x, (v.y-mu)*inv*gg.y+bb.y,
                  (v.z-mu)*inv*gg.z+bb.z, (v.w-mu)*inv*gg.w+bb.w };
    *(float4*)(out + (long)m*128 + lane*4) = o4;
}

/* ------- generic GEMM: C[m,n] = sum_k A[wrap(m,shift),k]*W[n,k]; M=32768 ------- */
__global__ __launch_bounds__(256) void gemm_kernel(
    const float* __restrict__ A, int lda, int shift,
    const float* __restrict__ W, int ldw,
    const float* __restrict__ bias,
    const float* __restrict__ res, int ldr,
    float* __restrict__ C, int ldc, int Kd, int flags)
{
    __shared__ __align__(16) float As[16][68], Ws[16][68];
    const int m0 = blockIdx.x*64, n0 = blockIdx.y*64;
    const int tid = threadIdx.x;
    const int row = tid >> 2, jj = (tid & 3)*4;
    const int tm = tid & 15, tn = tid >> 4;
    float acc[4][4];
    #pragma unroll
    for (int i = 0; i < 4; i++)
        #pragma unroll
        for (int j = 0; j < 4; j++) acc[i][j] = 0.f;
    int m = m0 + row;
    int msrc = (m & ~511) | ((m + shift) & 511);
    const float* Ap = A + (long)msrc*lda + jj;
    const float* Wp = W + (long)(n0+row)*ldw + jj;
    for (int k0 = 0; k0 < Kd; k0 += 16) {
        float4 av = *(const float4*)(Ap + k0);
        float4 wv = *(const float4*)(Wp + k0);
        As[jj+0][row]=av.x; As[jj+1][row]=av.y; As[jj+2][row]=av.z; As[jj+3][row]=av.w;
        Ws[jj+0][row]=wv.x; Ws[jj+1][row]=wv.y; Ws[jj+2][row]=wv.z; Ws[jj+3][row]=wv.w;
        __syncthreads();
        #pragma unroll
        for (int kk = 0; kk < 16; kk++) {
            float4 a = *(const float4*)&As[kk][tm*4];
            float4 b = *(const float4*)&Ws[kk][tn*4];
            float ar[4]={a.x,a.y,a.z,a.w}, br[4]={b.x,b.y,b.z,b.w};
            #pragma unroll
            for (int i = 0; i < 4; i++)
                #pragma unroll
                for (int j = 0; j < 4; j++) acc[i][j] = fmaf(ar[i], br[j], acc[i][j]);
        }
        __syncthreads();
    }
    #pragma unroll
    for (int i = 0; i < 4; i++) {
        int mm = m0 + tm*4 + i;
        float* Cr = C + (long)mm*ldc + n0 + tn*4;
        #pragma unroll
        for (int j = 0; j < 4; j++) {
            float v = acc[i][j];
            if (bias) v += bias[n0 + tn*4 + j];
            if (flags & ACCF)  v += Cr[j];
            if (flags & RELUF) v = fmaxf(v, 0.f);
            if (flags & RESF)  v += res[(long)mm*ldr + n0 + tn*4 + j];
            Cr[j] = v;
        }
    }
}

/* ------- fused attention, block = (b, head, 64-query tile) ------- */
#define ATTN_SMEM ((512*40 + 64*40 + 64*513)*4)
__global__ __launch_bounds__(256) void attn_kernel(const float* __restrict__ qkv,
                                                   float* __restrict__ r)
{
    extern __shared__ __align__(16) float sm[];
    float* ks = sm;
    float* qs = sm + 512*40;
    float* sc = sm + 512*40 + 64*40;
    const int qt = blockIdx.x, h = blockIdx.y, b = blockIdx.z;
    const int tid = threadIdx.x;
    const float* base = qkv + (long)b*512*768;

    for (int idx = tid; idx < 512*8; idx += 256) {
        int row = idx >> 3, j = idx & 7;
        *(float4*)&ks[row*40 + j*4] =
            *(const float4*)(base + (long)row*768 + 128 + h*32 + j*4);
    }
    for (int idx = tid; idx < 64*8; idx += 256) {
        int row = idx >> 3, j = idx & 7;
        *(float4*)&qs[row*40 + j*4] =
            *(const float4*)(base + (long)(qt*64+row)*768 + h*32 + j*4);
    }
    __syncthreads();
    {   /* scores */
        const int q = tid & 63, kc = tid >> 6;
        float qr[32];
        #pragma unroll
        for (int i = 0; i < 8; i++) {
            float4 v = *(const float4*)&qs[q*40 + i*4];
            qr[i*4]=v.x; qr[i*4+1]=v.y; qr[i*4+2]=v.z; qr[i*4+3]=v.w;
        }
        for (int k = kc*128; k < kc*128 + 128; k++) {
            float s0=0.f,s1=0.f,s2=0.f,s3=0.f;
            #pragma unroll
            for (int i = 0; i < 8; i++) {
                float4 kv = *(const float4*)&ks[k*40 + i*4];
                s0 = fmaf(qr[i*4+0], kv.x, s0);
                s1 = fmaf(qr[i*4+1], kv.y, s1);
                s2 = fmaf(qr[i*4+2], kv.z, s2);
                s3 = fmaf(qr[i*4+3], kv.w, s3);
            }
            sc[q*513 + k] = (s0+s1) + (s2+s3);
        }
    }
    __syncthreads();
    {   /* softmax, warp per row */
        const int warp = tid >> 5, lane = tid & 31;
        const float scale = 0.17677669529663689f;
        for (int row = warp; row < 64; row += 8) {
            float* sr = sc + row*513;
            float mx = -1e30f;
            for (int i = lane; i < 512; i += 32) mx = fmaxf(mx, sr[i]);
            #pragma unroll
            for (int o = 16; o; o >>= 1) mx = fmaxf(mx, __shfl_xor_sync(~0u, mx, o));
            float sum = 0.f;
            for (int i = lane; i < 512; i += 32) {
                float e = __expf((sr[i] - mx)*scale);
                sr[i] = e; sum += e;
            }
            #pragma unroll
            for (int o = 16; o; o >>= 1) sum += __shfl_xor_sync(~0u, sum, o);
            float inv = 1.f / sum;
            for (int i = lane; i < 512; i += 32) sr[i] *= inv;
        }
    }
    /* AV: V streamed in 4 chunks of 128 keys into ks region */
    const int qg = tid >> 4, cg = tid & 15;
    float acc[4][8];
    #pragma unroll
    for (int i = 0; i < 4; i++)
        #pragma unroll
        for (int j = 0; j < 8; j++) acc[i][j] = 0.f;
    for (int kc = 0; kc < 4; kc++) {
        __syncthreads();
        for (int idx = tid; idx < 128*32; idx += 256) {
            int row = idx >> 5, j = idx & 31;
            *(float4*)&ks[row*136 + j*4] =
                *(const float4*)(base + (long)(kc*128+row)*768 + 256 + h*128 + j*4);
        }
        __syncthreads();
        for (int k = 0; k < 128; k++) {
            float4 v0 = *(const float4*)&ks[k*136 + cg*8];
            float4 v1 = *(const float4*)&ks[k*136 + cg*8 + 4];
            int kk = kc*128 + k;
            #pragma unroll
            for (int qq = 0; qq < 4; qq++) {
                float p = sc[(qg*4+qq)*513 + kk];
                acc[qq][0]=fmaf(p,v0.x,acc[qq][0]); acc[qq][1]=fmaf(p,v0.y,acc[qq][1]);
                acc[qq][2]=fmaf(p,v0.z,acc[qq][2]); acc[qq][3]=fmaf(p,v0.w,acc[qq][3]);
                acc[qq][4]=fmaf(p,v1.x,acc[qq][4]); acc[qq][5]=fmaf(p,v1.y,acc[qq][5]);
                acc[qq][6]=fmaf(p,v1.z,acc[qq][6]); acc[qq][7]=fmaf(p,v1.w,acc[qq][7]);
            }
        }
    }
    #pragma unroll
    for (int qq = 0; qq < 4; qq++) {
        float* rp = r + ((long)(b*512 + qt*64 + qg*4 + qq))*512 + h*128 + cg*8;
        float4 w0 = {acc[qq][0],acc[qq][1],acc[qq][2],acc[qq][3]};
        float4 w1 = {acc[qq][4],acc[qq][5],acc[qq][6],acc[qq][7]};
        *(float4*)rp = w0; *(float4*)(rp+4) = w1;
    }
}

/* ------- fus max over K + broadcast into FEAT cols [256,512) ------- */
__global__ void maxg_kernel(const float* __restrict__ fus, float* __restrict__ feat)
{
    int b = blockIdx.x, o = threadIdx.x;
    float m = -1e30f;
    for (int k = 0; k < 512; k++)
        m = fmaxf(m, fus[((long)b*512 + k)*256 + o]);
    for (int k = 0; k < 512; k++)
        feat[((long)b*512 + k)*1536 + 256 + o] = m;
}

__device__ __forceinline__ float sigf(float x) { return 1.f/(1.f + __expf(-x)); }

__global__ void lstm_kernel(const float* __restrict__ g, const float* __restrict__ c0,
                            float* __restrict__ feat, float* __restrict__ oh,
                            float* __restrict__ oc)
{
    long row = blockIdx.x; int j = threadIdx.x;
    const float* gr = g + row*1024;
    float gi = gr[j], gf = gr[256+j], gg = gr[512+j], go = gr[768+j];
    float c = sigf(gf)*c0[row*256 + j] + sigf(gi)*tanhf(gg);
    float hh = sigf(go)*tanhf(c);
    oh[row*256 + j] = hh;
    oc[row*256 + j] = c;
    feat[row*1536 + j] = hh;
}

/* ------- final 64->2 projection, out p (B,2,K) ------- */
__global__ void p3_kernel(const float* __restrict__ p2, const float* __restrict__ w,
                          const float* __restrict__ bias, float* __restrict__ out)
{
    __shared__ float ws[128];
    int b = blockIdx.x, k = threadIdx.x;
    if (k < 128) ws[k] = w[k];
    __syncthreads();
    const float* pr = p2 + (long)(b*512 + k)*64;
    float s0 = bias[0], s1 = bias[1];
    for (int c = 0; c < 64; c++) {
        float v = pr[c];
        s0 = fmaf(v, ws[c], s0);
        s1 = fmaf(v, ws[64+c], s1);
    }
    out[(long)b*1024 + k]       = s0;
    out[(long)b*1024 + 512 + k] = s1;
}

static const int DILS[8] = {1,1,1,1,2,2,4,4};

extern "C" void kernel_launch(void* const* d_in, const int* in_sizes, int n_in,
                              void* d_out, int out_size)
{
    const float *x=(const float*)d_in[0], *h0=(const float*)d_in[1], *c0=(const float*)d_in[2];
    const float *ln_g=(const float*)d_in[3], *ln_b=(const float*)d_in[4];
    const float *Wq=(const float*)d_in[5], *Wk=(const float*)d_in[6], *Wv=(const float*)d_in[7];
    const float *Ww=(const float*)d_in[8], *Wa=(const float*)d_in[9];
    const float *cw=(const float*)d_in[10], *cb=(const float*)d_in[11];
    const float *fus_w=(const float*)d_in[12], *fus_b=(const float*)d_in[13];
    const float *rs_w=(const float*)d_in[14], *rs_b=(const float*)d_in[15];
    const float *W_ih=(const float*)d_in[16], *W_hh=(const float*)d_in[17];
    const float *b_ih=(const float*)d_in[18], *b_hh=(const float*)d_in[19];
    const float *p1_w=(const float*)d_in[20], *p1_b=(const float*)d_in[21];
    const float *p2_w=(const float*)d_in[22], *p2_b=(const float*)d_in[23];
    const float *p3_w=(const float*)d_in[24], *p3_b=(const float*)d_in[25];
    float* out = (float*)d_out;

    float* buf; cudaGetSymbolAddress((void**)&buf, BUF);
    float *LN=buf+O_LN, *QKV=buf+O_QKV, *R=buf+O_R, *TMP=buf+O_TMP, *XT=buf+O_XT;
    float *FEAT=buf+O_FEAT, *FUS=buf+O_FUS, *GATES=buf+O_GATES, *P1=buf+O_P1, *P2=buf+O_P2;
    float *WQKV=buf+O_WQKV, *WCONV=buf+O_WCONV, *WC=buf+O_WC, *WAB=buf+O_WAB;

    cudaFuncSetAttribute(attn_kernel, cudaFuncAttributeMaxDynamicSharedMemorySize, ATTN_SMEM);

    prep_qkv<<<dim3(768,8),128>>>(Wq, Wk, Wv, WQKV);
    prep_wc<<<dim3(512,8),128>>>(Ww, Wa, WC);
    prep_wab<<<dim3(128,8),128>>>(Wa, WAB);
    prep_conv<<<dim3(1152,8),128>>>(cw, WCONV);
    transpose_x<<<dim3(16,4,64),dim3(32,8)>>>(x, XT);

    for (int i = 0; i < 8; i++) {
        const float* in = (i == 0) ? XT : FEAT + 512 + 128*(i-1);
        int ldin = (i == 0) ? 128 : 1536;
        float* hout = FEAT + 512 + 128*i;
        ln_kernel<<<4096,256>>>(in, ldin, ln_g + i*128, ln_b + i*128, LN);
        gemm_kernel<<<dim3(512,12),256>>>(LN,128,0, WQKV+(long)i*768*128,128,
                                          nullptr, nullptr,0, QKV,768, 128, 0);
        attn_kernel<<<dim3(8,4,64),256,ATTN_SMEM>>>(QKV, R);
        gemm_kernel<<<dim3(512,2),256>>>(R,512,0, WC+(long)i*128*512,512,
                                         nullptr, nullptr,0, TMP,128, 512, 0);
        gemm_kernel<<<dim3(512,2),256>>>(in,ldin,0, WAB+(long)i*128*128,128,
                                         nullptr, nullptr,0, TMP,128, 128, ACCF);
        for (int t = 0; t < 9; t++) {
            int flags = (t ? ACCF : 0);
            const float* bias = nullptr; const float* res = nullptr;
            if (t == 8) {
                flags |= RELUF; bias = cb + i*128;
                if (i > 0) { flags |= RESF; res = FEAT + 512 + 128*(i-1); }
            }
            gemm_kernel<<<dim3(512,2),256>>>(TMP,128,(t-4)*DILS[i],
                WCONV+((long)i*9+t)*16384,128, bias, res,1536, hout,1536, 128, flags);
        }
    }
    /* tail */
    gemm_kernel<<<dim3(512,4),256>>>(FEAT+512,1536,0, fus_w,1024, fus_b,
                                     nullptr,0, FUS,256, 1024, 0);
    maxg_kernel<<<64,256>>>(FUS, FEAT);
    gemm_kernel<<<dim3(512,4),256>>>(FEAT+256,1536,0, rs_w,1280, rs_b,
                                     nullptr,0, QKV,256, 1280, 0);   /* reuse QKV as rnn_in */
    gemm_kernel<<<dim3(512,16),256>>>(QKV,256,0, W_ih,256, b_ih,
                                      nullptr,0, GATES,1024, 256, 0);
    gemm_kernel<<<dim3(512,16),256>>>(h0,256,0, W_hh,256, b_hh,
                                      nullptr,0, GATES,1024, 256, ACCF);
    lstm_kernel<<<32768,256>>>(GATES, c0, FEAT, out + 65536, out + 65536 + 8388608);
    gemm_kernel<<<dim3(512,4),256>>>(FEAT,1536,0, p1_w,1536, p1_b,
                                     nullptr,0, P1,256, 1536, RELUF);
    gemm_kernel<<<dim3(512,1),256>>>(P1,256,0, p2_w,256, p2_b,
                                     nullptr,0, P2,64, 256, RELUF);
    p3_kernel<<<64,512>>>(P2, p3_w, p3_b, out);
}

// round 6
// speedup vs baseline: 1.2878x; 1.2878x over previous
#include <cuda_runtime.h>
#include <math.h>

#define RELUF 1
#define RESF  4
#define TK 16

typedef unsigned long long u64;
__device__ __forceinline__ void fma2(u64 &d, u64 a, u64 b) {
    asm("fma.rn.f32x2 %0, %1, %2, %0;" : "+l"(d) : "l"(a), "l"(b));
}
__device__ __forceinline__ void add2(u64 &d, u64 a) {
    asm("add.rn.f32x2 %0, %0, %1;" : "+l"(d) : "l"(a));
}
__device__ __forceinline__ u64 dup2(float x) {
    u64 r; asm("mov.b64 %0, {%1, %1};" : "=l"(r) : "f"(x)); return r;
}
__device__ __forceinline__ float2 unp2(u64 v) {
    float2 r; asm("mov.b64 {%0, %1}, %2;" : "=f"(r.x), "=f"(r.y) : "l"(v)); return r;
}

/* scratch offsets in floats */
#define O_LN    0ul
#define O_QKV   4194304ul
#define O_R     29360128ul
#define O_TMP   46137344ul
#define O_XT    50331648ul
#define O_FEAT  54525952ul
#define O_FUS   104857600ul
#define O_GATES 113246208ul
#define O_P1    146800640ul
#define O_P2    155189248ul
#define O_WQKV  157286400ul
#define O_WCONV 158072832ul
#define O_WCB   159252480ul
#define O_WG    159907840ul
#define O_BG    160432128ul
#define BUFSZ   160433152ul

__device__ __align__(256) float BUF[BUFSZ];

/* ---------------- weight prep ---------------- */
__global__ void prep_qkv(const float* __restrict__ Wq, const float* __restrict__ Wk,
                         const float* __restrict__ Wv, float* __restrict__ o)
{
    int n = blockIdx.x, l = blockIdx.y, k = threadIdx.x;
    float v;
    if (n < 128)      v = Wq[((long)l*128 + k)*128 + n];
    else if (n < 256) v = Wk[((long)l*128 + k)*128 + (n-128)];
    else              v = Wv[((long)l*128 + k)*512 + (n-256)];
    o[((long)l*768 + n)*128 + k] = v;
}
/* WCB[l][n][0:512] = (Ww @ Wa_top)^T fold */
__global__ void prep_wc(const float* __restrict__ Ww, const float* __restrict__ Wa,
                        float* __restrict__ o)
{
    int i = blockIdx.x, l = blockIdx.y, n = threadIdx.x;
    float s = 0.f;
    for (int j = 0; j < 128; j++)
        s = fmaf(Ww[((long)l*512 + i)*128 + j], Wa[((long)l*256 + j)*128 + n], s);
    o[((long)l*128 + n)*640 + i] = s;
}
/* WCB[l][n][512:640] = Wa_bottom^T */
__global__ void prep_wab(const float* __restrict__ Wa, float* __restrict__ o)
{
    int i = blockIdx.x, l = blockIdx.y, n = threadIdx.x;
    o[((long)l*128 + n)*640 + 512 + i] = Wa[((long)l*256 + 128 + i)*128 + n];
}
/* WCONV[l][oc][t*128+c] */
__global__ void prep_conv(const float* __restrict__ cw, float* __restrict__ o)
{
    int t = blockIdx.x >> 7, oc = blockIdx.x & 127, l = blockIdx.y, c = threadIdx.x;
    o[((long)l*128 + oc)*1152 + t*128 + c] = cw[(((long)l*128 + oc)*128 + c)*9 + t];
}
/* WG[n][0:256]=W_ih[n], [256:512]=W_hh[n]; bg=b_ih+b_hh */
__global__ void prep_wg(const float* __restrict__ Wih, const float* __restrict__ Whh,
                        const float* __restrict__ bih, const float* __restrict__ bhh,
                        float* __restrict__ wg, float* __restrict__ bg)
{
    int n = blockIdx.x, j = threadIdx.x;
    wg[(long)n*512 + j] = (j < 256) ? Wih[(long)n*256 + j] : Whh[(long)n*256 + (j-256)];
    if (j == 0) bg[n] = bih[n] + bhh[n];
}
/* x (B,C,K) -> XT (B,K,C) */
__global__ void transpose_x(const float* __restrict__ x, float* __restrict__ xt)
{
    __shared__ float t[32][33];
    int b = blockIdx.z, k0 = blockIdx.x*32, c0 = blockIdx.y*32;
    int tx = threadIdx.x, ty = threadIdx.y;
    const float* xb = x + (long)b*128*512;
    #pragma unroll
    for (int i = 0; i < 32; i += 8) t[ty+i][tx] = xb[(long)(c0+ty+i)*512 + k0+tx];
    __syncthreads();
    float* xo = xt + (long)b*512*128;
    #pragma unroll
    for (int i = 0; i < 32; i += 8) xo[(long)(k0+ty+i)*128 + c0+tx] = t[tx][ty+i];
}

/* ---------------- layernorm ---------------- */
__global__ __launch_bounds__(256) void ln_kernel(const float* __restrict__ in, int lda,
                                                 const float* __restrict__ g,
                                                 const float* __restrict__ bt,
                                                 float* __restrict__ out)
{
    int m = blockIdx.x*8 + (threadIdx.x >> 5);
    int lane = threadIdx.x & 31;
    float4 v = *(const float4*)(in + (long)m*lda + lane*4);
    float s = v.x+v.y+v.z+v.w, sq = v.x*v.x+v.y*v.y+v.z*v.z+v.w*v.w;
    #pragma unroll
    for (int o = 16; o; o >>= 1) {
        s  += __shfl_xor_sync(~0u, s,  o);
        sq += __shfl_xor_sync(~0u, sq, o);
    }
    float mu = s*(1.f/128.f), var = sq*(1.f/128.f) - mu*mu;
    float inv = rsqrtf(var + 1e-6f);
    float4 gg = *(const float4*)(g + lane*4), bb = *(const float4*)(bt + lane*4);
    float4 o4 = { (v.x-mu)*inv*gg.x+bb.x, (v.y-mu)*inv*gg.y+bb.y,
                  (v.z-mu)*inv*gg.z+bb.z, (v.w-mu)*inv*gg.w+bb.w };
    *(float4*)(out + (long)m*128 + lane*4) = o4;
}

/* ------- 128x128-tile f32x2 GEMM: C = A(+A2 split)(conv-shift) @ W^T ------- */
__global__ __launch_bounds__(256) void gemm2(
    const float* __restrict__ A, int lda,
    const float* __restrict__ A2, int lda2, int splitK,
    const float* __restrict__ W, int ldw,
    const float* __restrict__ bias,
    const float* __restrict__ res, int ldr,
    float* __restrict__ C, int ldc,
    int Kd, int dil, int flags)
{
    __shared__ __align__(16) float As[TK][132], Ws[TK][132];
    const int m0 = blockIdx.x*128, n0 = blockIdx.y*128;
    const int tid = threadIdx.x;
    const int lrow = tid >> 2, ljj = (tid & 3)*4;
    const int tm = tid & 15, tn = tid >> 4;

    u64 acc[8][4];
    #pragma unroll
    for (int i = 0; i < 8; i++)
        #pragma unroll
        for (int j = 0; j < 4; j++) acc[i][j] = 0ull;

    auto fA = [&](int k0, int r) -> float4 {
        const float* src = A; int ld = lda; int kk = k0;
        if (splitK && k0 >= splitK) { src = A2; ld = lda2; kk = k0 - splitK; }
        int m = m0 + r;
        if (dil) {
            int t = k0 >> 7;
            m = (m & ~511) | ((m + (t-4)*dil) & 511);
            kk = k0 & 127;
        }
        return *(const float4*)(src + (long)m*ld + kk + ljj);
    };
    auto fW = [&](int k0, int r) -> float4 {
        return *(const float4*)(W + (long)(n0+r)*ldw + k0 + ljj);
    };

    float4 pa0 = fA(0, lrow), pa1 = fA(0, lrow+64);
    float4 pw0 = fW(0, lrow), pw1 = fW(0, lrow+64);

    for (int k0 = 0; k0 < Kd; k0 += TK) {
        As[ljj+0][lrow]=pa0.x; As[ljj+1][lrow]=pa0.y; As[ljj+2][lrow]=pa0.z; As[ljj+3][lrow]=pa0.w;
        As[ljj+0][lrow+64]=pa1.x; As[ljj+1][lrow+64]=pa1.y; As[ljj+2][lrow+64]=pa1.z; As[ljj+3][lrow+64]=pa1.w;
        Ws[ljj+0][lrow]=pw0.x; Ws[ljj+1][lrow]=pw0.y; Ws[ljj+2][lrow]=pw0.z; Ws[ljj+3][lrow]=pw0.w;
        Ws[ljj+0][lrow+64]=pw1.x; Ws[ljj+1][lrow+64]=pw1.y; Ws[ljj+2][lrow+64]=pw1.z; Ws[ljj+3][lrow+64]=pw1.w;
        __syncthreads();
        if (k0 + TK < Kd) {
            pa0 = fA(k0+TK, lrow); pa1 = fA(k0+TK, lrow+64);
            pw0 = fW(k0+TK, lrow); pw1 = fW(k0+TK, lrow+64);
        }
        #pragma unroll
        for (int kk = 0; kk < TK; kk++) {
            float4 a0 = *(const float4*)&As[kk][tm*8];
            float4 a1 = *(const float4*)&As[kk][tm*8+4];
            ulonglong2 b0 = *(const ulonglong2*)&Ws[kk][tn*8];
            ulonglong2 b1 = *(const ulonglong2*)&Ws[kk][tn*8+4];
            u64 ad[8];
            ad[0]=dup2(a0.x); ad[1]=dup2(a0.y); ad[2]=dup2(a0.z); ad[3]=dup2(a0.w);
            ad[4]=dup2(a1.x); ad[5]=dup2(a1.y); ad[6]=dup2(a1.z); ad[7]=dup2(a1.w);
            #pragma unroll
            for (int i = 0; i < 8; i++) {
                fma2(acc[i][0], ad[i], b0.x);
                fma2(acc[i][1], ad[i], b0.y);
                fma2(acc[i][2], ad[i], b1.x);
                fma2(acc[i][3], ad[i], b1.y);
            }
        }
        __syncthreads();
    }

    #pragma unroll
    for (int i = 0; i < 8; i++) {
        int mm = m0 + tm*8 + i;
        float* Cr = C + (long)mm*ldc + n0 + tn*8;
        float o[8];
        #pragma unroll
        for (int jp = 0; jp < 4; jp++) {
            float2 f = unp2(acc[i][jp]);
            o[2*jp] = f.x; o[2*jp+1] = f.y;
        }
        #pragma unroll
        for (int j = 0; j < 8; j++) {
            float v = o[j];
            if (bias) v += bias[n0 + tn*8 + j];
            if (flags & RELUF) v = fmaxf(v, 0.f);
            if (flags & RESF)  v += res[(long)mm*ldr + n0 + tn*8 + j];
            o[j] = v;
        }
        float4 w0 = {o[0],o[1],o[2],o[3]}, w1 = {o[4],o[5],o[6],o[7]};
        *(float4*)Cr = w0; *(float4*)(Cr+4) = w1;
    }
}

/* ------- old 64x64 GEMM kept for small-N (p2) ------- */
__global__ __launch_bounds__(256) void gemm_kernel(
    const float* __restrict__ A, int lda,
    const float* __restrict__ W, int ldw,
    const float* __restrict__ bias,
    float* __restrict__ C, int ldc, int Kd, int flags)
{
    __shared__ __align__(16) float As[16][68], Ws[16][68];
    const int m0 = blockIdx.x*64, n0 = blockIdx.y*64;
    const int tid = threadIdx.x;
    const int row = tid >> 2, jj = (tid & 3)*4;
    const int tm = tid & 15, tn = tid >> 4;
    float acc[4][4];
    #pragma unroll
    for (int i = 0; i < 4; i++)
        #pragma unroll
        for (int j = 0; j < 4; j++) acc[i][j] = 0.f;
    const float* Ap = A + (long)(m0+row)*lda + jj;
    const float* Wp = W + (long)(n0+row)*ldw + jj;
    for (int k0 = 0; k0 < Kd; k0 += 16) {
        float4 av = *(const float4*)(Ap + k0);
        float4 wv = *(const float4*)(Wp + k0);
        As[jj+0][row]=av.x; As[jj+1][row]=av.y; As[jj+2][row]=av.z; As[jj+3][row]=av.w;
        Ws[jj+0][row]=wv.x; Ws[jj+1][row]=wv.y; Ws[jj+2][row]=wv.z; Ws[jj+3][row]=wv.w;
        __syncthreads();
        #pragma unroll
        for (int kk = 0; kk < 16; kk++) {
            float4 a = *(const float4*)&As[kk][tm*4];
            float4 b = *(const float4*)&Ws[kk][tn*4];
            float ar[4]={a.x,a.y,a.z,a.w}, br[4]={b.x,b.y,b.z,b.w};
            #pragma unroll
            for (int i = 0; i < 4; i++)
                #pragma unroll
                for (int j = 0; j < 4; j++) acc[i][j] = fmaf(ar[i], br[j], acc[i][j]);
        }
        __syncthreads();
    }
    #pragma unroll
    for (int i = 0; i < 4; i++) {
        int mm = m0 + tm*4 + i;
        float* Cr = C + (long)mm*ldc + n0 + tn*4;
        #pragma unroll
        for (int j = 0; j < 4; j++) {
            float v = acc[i][j];
            if (bias) v += bias[n0 + tn*4 + j];
            if (flags & RELUF) v = fmaxf(v, 0.f);
            Cr[j] = v;
        }
    }
}

/* ------- fused attention, block = (b, head, 64-query tile), f32x2 packed ------- */
#define ATTN_SMEM ((512*40 + 64*40 + 64*513)*4)
__global__ __launch_bounds__(256) void attn_kernel(const float* __restrict__ qkv,
                                                   float* __restrict__ r)
{
    extern __shared__ __align__(16) float sm[];
    float* ks = sm;
    float* qs = sm + 512*40;
    float* sc = sm + 512*40 + 64*40;
    const int qt = blockIdx.x, h = blockIdx.y, b = blockIdx.z;
    const int tid = threadIdx.x;
    const float* base = qkv + (long)b*512*768;

    for (int idx = tid; idx < 512*8; idx += 256) {
        int row = idx >> 3, j = idx & 7;
        *(float4*)&ks[row*40 + j*4] =
            *(const float4*)(base + (long)row*768 + 128 + h*32 + j*4);
    }
    for (int idx = tid; idx < 64*8; idx += 256) {
        int row = idx >> 3, j = idx & 7;
        *(float4*)&qs[row*40 + j*4] =
            *(const float4*)(base + (long)(qt*64+row)*768 + h*32 + j*4);
    }
    __syncthreads();
    {   /* scores: q=tid&63, kc quarter; packed along d */
        const int q = tid & 63, kc = tid >> 6;
        ulonglong2 qv[4];
        #pragma unroll
        for (int i = 0; i < 4; i++)
            qv[i] = *(const ulonglong2*)&qs[q*40 + i*8];
        ulonglong2 qv2[4];
        #pragma unroll
        for (int i = 0; i < 4; i++)
            qv2[i] = *(const ulonglong2*)&qs[q*40 + i*8 + 4];
        for (int k = kc*128; k < kc*128 + 128; k++) {
            u64 a0=0ull, a1=0ull, a2=0ull, a3=0ull;
            #pragma unroll
            for (int i = 0; i < 4; i++) {
                ulonglong2 kv0 = *(const ulonglong2*)&ks[k*40 + i*8];
                ulonglong2 kv1 = *(const ulonglong2*)&ks[k*40 + i*8 + 4];
                fma2(a0, qv[i].x,  kv0.x);
                fma2(a1, qv[i].y,  kv0.y);
                fma2(a2, qv2[i].x, kv1.x);
                fma2(a3, qv2[i].y, kv1.y);
            }
            add2(a0, a2); add2(a1, a3); add2(a0, a1);
            float2 f = unp2(a0);
            sc[q*513 + k] = f.x + f.y;
        }
    }
    __syncthreads();
    {   /* softmax */
        const int warp = tid >> 5, lane = tid & 31;
        const float scale = 0.17677669529663689f;
        for (int row = warp; row < 64; row += 8) {
            float* sr = sc + row*513;
            float mx = -1e30f;
            for (int i = lane; i < 512; i += 32) mx = fmaxf(mx, sr[i]);
            #pragma unroll
            for (int o = 16; o; o >>= 1) mx = fmaxf(mx, __shfl_xor_sync(~0u, mx, o));
            float sum = 0.f;
            for (int i = lane; i < 512; i += 32) {
                float e = __expf((sr[i] - mx)*scale);
                sr[i] = e; sum += e;
            }
            #pragma unroll
            for (int o = 16; o; o >>= 1) sum += __shfl_xor_sync(~0u, sum, o);
            float inv = 1.f / sum;
            for (int i = lane; i < 512; i += 32) sr[i] *= inv;
        }
    }
    /* AV: V streamed in 4 chunks of 128 keys; packed along channel */
    const int qg = tid >> 4, cg = tid & 15;
    u64 acc[4][4];
    #pragma unroll
    for (int i = 0; i < 4; i++)
        #pragma unroll
        for (int j = 0; j < 4; j++) acc[i][j] = 0ull;
    for (int kc = 0; kc < 4; kc++) {
        __syncthreads();
        for (int idx = tid; idx < 128*32; idx += 256) {
            int row = idx >> 5, j = idx & 31;
            *(float4*)&ks[row*136 + j*4] =
                *(const float4*)(base + (long)(kc*128+row)*768 + 256 + h*128 + j*4);
        }
        __syncthreads();
        for (int k = 0; k < 128; k++) {
            ulonglong2 v0 = *(const ulonglong2*)&ks[k*136 + cg*8];
            ulonglong2 v1 = *(const ulonglong2*)&ks[k*136 + cg*8 + 4];
            int kk = kc*128 + k;
            #pragma unroll
            for (int qq = 0; qq < 4; qq++) {
                u64 pd = dup2(sc[(qg*4+qq)*513 + kk]);
                fma2(acc[qq][0], pd, v0.x);
                fma2(acc[qq][1], pd, v0.y);
                fma2(acc[qq][2], pd, v1.x);
                fma2(acc[qq][3], pd, v1.y);
            }
        }
    }
    #pragma unroll
    for (int qq = 0; qq < 4; qq++) {
        float* rp = r + ((long)(b*512 + qt*64 + qg*4 + qq))*512 + h*128 + cg*8;
        float2 c0 = unp2(acc[qq][0]), c1 = unp2(acc[qq][1]);
        float2 c2 = unp2(acc[qq][2]), c3 = unp2(acc[qq][3]);
        float4 w0 = {c0.x,c0.y,c1.x,c1.y}, w1 = {c2.x,c2.y,c3.x,c3.y};
        *(float4*)rp = w0; *(float4*)(rp+4) = w1;
    }
}

/* ------- fus max over K + broadcast ------- */
__global__ void maxg_kernel(const float* __restrict__ fus, float* __restrict__ feat)
{
    int b = blockIdx.x, o = threadIdx.x;
    float m = -1e30f;
    for (int k = 0; k < 512; k++)
        m = fmaxf(m, fus[((long)b*512 + k)*256 + o]);
    for (int k = 0; k < 512; k++)
        feat[((long)b*512 + k)*1536 + 256 + o] = m;
}

__device__ __forceinline__ float sigf(float x) { return 1.f/(1.f + __expf(-x)); }

__global__ void lstm_kernel(const float* __restrict__ g, const float* __restrict__ c0,
                            float* __restrict__ feat, float* __restrict__ oh,
                            float* __restrict__ oc)
{
    long row = blockIdx.x; int j = threadIdx.x;
    const float* gr = g + row*1024;
    float gi = gr[j], gf = gr[256+j], gg = gr[512+j], go = gr[768+j];
    float c = sigf(gf)*c0[row*256 + j] + sigf(gi)*tanhf(gg);
    float hh = sigf(go)*tanhf(c);
    oh[row*256 + j] = hh;
    oc[row*256 + j] = c;
    feat[row*1536 + j] = hh;
}

__global__ void p3_kernel(const float* __restrict__ p2, const float* __restrict__ w,
                          const float* __restrict__ bias, float* __restrict__ out)
{
    __shared__ float ws[128];
    int b = blockIdx.x, k = threadIdx.x;
    if (k < 128) ws[k] = w[k];
    __syncthreads();
    const float* pr = p2 + (long)(b*512 + k)*64;
    float s0 = bias[0], s1 = bias[1];
    for (int c = 0; c < 64; c++) {
        float v = pr[c];
        s0 = fmaf(v, ws[c], s0);
        s1 = fmaf(v, ws[64+c], s1);
    }
    out[(long)b*1024 + k]       = s0;
    out[(long)b*1024 + 512 + k] = s1;
}

static const int DILS[8] = {1,1,1,1,2,2,4,4};

extern "C" void kernel_launch(void* const* d_in, const int* in_sizes, int n_in,
                              void* d_out, int out_size)
{
    const float *x=(const float*)d_in[0], *h0=(const float*)d_in[1], *c0=(const float*)d_in[2];
    const float *ln_g=(const float*)d_in[3], *ln_b=(const float*)d_in[4];
    const float *Wq=(const float*)d_in[5], *Wk=(const float*)d_in[6], *Wv=(const float*)d_in[7];
    const float *Ww=(const float*)d_in[8], *Wa=(const float*)d_in[9];
    const float *cw=(const float*)d_in[10], *cb=(const float*)d_in[11];
    const float *fus_w=(const float*)d_in[12], *fus_b=(const float*)d_in[13];
    const float *rs_w=(const float*)d_in[14], *rs_b=(const float*)d_in[15];
    const float *W_ih=(const float*)d_in[16], *W_hh=(const float*)d_in[17];
    const float *b_ih=(const float*)d_in[18], *b_hh=(const float*)d_in[19];
    const float *p1_w=(const float*)d_in[20], *p1_b=(const float*)d_in[21];
    const float *p2_w=(const float*)d_in[22], *p2_b=(const float*)d_in[23];
    const float *p3_w=(const float*)d_in[24], *p3_b=(const float*)d_in[25];
    float* out = (float*)d_out;

    float* buf; cudaGetSymbolAddress((void**)&buf, BUF);
    float *LN=buf+O_LN, *QKV=buf+O_QKV, *R=buf+O_R, *TMP=buf+O_TMP, *XT=buf+O_XT;
    float *FEAT=buf+O_FEAT, *FUS=buf+O_FUS, *GATES=buf+O_GATES, *P1=buf+O_P1, *P2=buf+O_P2;
    float *WQKV=buf+O_WQKV, *WCONV=buf+O_WCONV, *WCB=buf+O_WCB, *WG=buf+O_WG, *BG=buf+O_BG;

    cudaFuncSetAttribute(attn_kernel, cudaFuncAttributeMaxDynamicSharedMemorySize, ATTN_SMEM);

    prep_qkv<<<dim3(768,8),128>>>(Wq, Wk, Wv, WQKV);
    prep_wc<<<dim3(512,8),128>>>(Ww, Wa, WCB);
    prep_wab<<<dim3(128,8),128>>>(Wa, WCB);
    prep_conv<<<dim3(1152,8),128>>>(cw, WCONV);
    prep_wg<<<1024,512>>>(W_ih, W_hh, b_ih, b_hh, WG, BG);
    transpose_x<<<dim3(16,4,64),dim3(32,8)>>>(x, XT);

    for (int i = 0; i < 8; i++) {
        const float* in = (i == 0) ? XT : FEAT + 512 + 128*(i-1);
        int ldin = (i == 0) ? 128 : 1536;
        float* hout = FEAT + 512 + 128*i;
        ln_kernel<<<4096,256>>>(in, ldin, ln_g + i*128, ln_b + i*128, LN);
        gemm2<<<dim3(256,6),256>>>(LN,128, nullptr,0,0, WQKV+(long)i*98304,128,
                                   nullptr, nullptr,0, QKV,768, 128, 0, 0);
        attn_kernel<<<dim3(8,4,64),256,ATTN_SMEM>>>(QKV, R);
        /* TMP = R @ Wc + in @ Wab  (split-K) */
        gemm2<<<dim3(256,1),256>>>(R,512, in,ldin,512, WCB+(long)i*81920,640,
                                   nullptr, nullptr,0, TMP,128, 640, 0, 0);
        /* conv: single GEMM K=1152 with per-tap circular shift */
        int flags = RELUF; const float* res = nullptr;
        if (i > 0) { flags |= RESF; res = FEAT + 512 + 128*(i-1); }
        gemm2<<<dim3(256,1),256>>>(TMP,128, nullptr,0,0, WCONV+(long)i*147456,1152,
                                   cb + i*128, res,1536, hout,1536, 1152, DILS[i], flags);
    }
    /* tail */
    gemm2<<<dim3(256,2),256>>>(FEAT+512,1536, nullptr,0,0, fus_w,1024, fus_b,
                               nullptr,0, FUS,256, 1024, 0, 0);
    maxg_kernel<<<64,256>>>(FUS, FEAT);
    gemm2<<<dim3(256,2),256>>>(FEAT+256,1536, nullptr,0,0, rs_w,1280, rs_b,
                               nullptr,0, QKV,256, 1280, 0, 0);
    /* gates = rnn_in @ W_ih^T + h0 @ W_hh^T + (b_ih+b_hh) */
    gemm2<<<dim3(256,8),256>>>(QKV,256, h0,256,256, WG,512, BG,
                               nullptr,0, GATES,1024, 512, 0, 0);
    lstm_kernel<<<32768,256>>>(GATES, c0, FEAT, out + 65536, out + 65536 + 8388608);
    gemm2<<<dim3(256,2),256>>>(FEAT,1536, nullptr,0,0, p1_w,1536, p1_b,
                               nullptr,0, P1,256, 1536, 0, RELUF);
    gemm_kernel<<<dim3(512,1),256>>>(P1,256, p2_w,256, p2_b, P2,64, 256, RELUF);
    p3_kernel<<<64,512>>>(P2, p3_w, p3_b, out);
}

// round 7
// speedup vs baseline: 1.2893x; 1.0011x over previous
#include <cuda_runtime.h>
#include <math.h>

#define RELUF 1
#define RESF  4
#define TK 16

typedef unsigned long long u64;
__device__ __forceinline__ void fma2(u64 &d, u64 a, u64 b) {
    asm("fma.rn.f32x2 %0, %1, %2, %0;" : "+l"(d) : "l"(a), "l"(b));
}
__device__ __forceinline__ void add2(u64 &d, u64 a) {
    asm("add.rn.f32x2 %0, %0, %1;" : "+l"(d) : "l"(a));
}
__device__ __forceinline__ u64 dup2(float x) {
    u64 r; asm("mov.b64 %0, {%1, %1};" : "=l"(r) : "f"(x)); return r;
}
__device__ __forceinline__ float2 unp2(u64 v) {
    float2 r; asm("mov.b64 {%0, %1}, %2;" : "=f"(r.x), "=f"(r.y) : "l"(v)); return r;
}

/* scratch offsets in floats */
#define O_LN    0ul
#define O_QKV   4194304ul
#define O_R     29360128ul
#define O_TMP   46137344ul
#define O_XT    50331648ul
#define O_FEAT  54525952ul
#define O_FUS   104857600ul
#define O_GATES 113246208ul
#define O_P1    146800640ul
#define O_P2    155189248ul
#define O_WQKV  157286400ul
#define O_WCONV 158072832ul
#define O_WCB   159252480ul
#define O_WG    159907840ul
#define O_BG    160432128ul
#define BUFSZ   160433152ul

__device__ __align__(256) float BUF[BUFSZ];

/* ---------------- single merged prep kernel (128 threads/block) ----------------
   block ranges: [0,6144) qkv | [6144,10240) wc | [10240,11264) wab
                 [11264,20480) conv | [20480,21504) wg | [21504,25600) transpose */
__global__ __launch_bounds__(128) void prep_all(
    const float* __restrict__ Wq, const float* __restrict__ Wk,
    const float* __restrict__ Wv, const float* __restrict__ Ww,
    const float* __restrict__ Wa, const float* __restrict__ cw,
    const float* __restrict__ Wih, const float* __restrict__ Whh,
    const float* __restrict__ bih, const float* __restrict__ bhh,
    const float* __restrict__ x,
    float* __restrict__ oqkv, float* __restrict__ owcb,
    float* __restrict__ oconv, float* __restrict__ owg,
    float* __restrict__ obg, float* __restrict__ oxt)
{
    int bid = blockIdx.x, thr = threadIdx.x;
    if (bid < 6144) {                     /* qkv pack */
        int n = bid % 768, l = bid / 768, k = thr;
        float v;
        if (n < 128)      v = Wq[((long)l*128 + k)*128 + n];
        else if (n < 256) v = Wk[((long)l*128 + k)*128 + (n-128)];
        else              v = Wv[((long)l*128 + k)*512 + (n-256)];
        oqkv[((long)l*768 + n)*128 + k] = v;
    } else if (bid < 10240) {             /* wc fold */
        int idx = bid - 6144, i = idx % 512, l = idx / 512, n = thr;
        float s = 0.f;
        for (int j = 0; j < 128; j++)
            s = fmaf(Ww[((long)l*512 + i)*128 + j], Wa[((long)l*256 + j)*128 + n], s);
        owcb[((long)l*128 + n)*640 + i] = s;
    } else if (bid < 11264) {             /* wab */
        int idx = bid - 10240, i = idx % 128, l = idx / 128, n = thr;
        owcb[((long)l*128 + n)*640 + 512 + i] = Wa[((long)l*256 + 128 + i)*128 + n];
    } else if (bid < 20480) {             /* conv transpose */
        int idx = bid - 11264, l = idx / 1152, rem = idx % 1152;
        int t = rem >> 7, oc = rem & 127, c = thr;
        oconv[((long)l*128 + oc)*1152 + t*128 + c] = cw[(((long)l*128 + oc)*128 + c)*9 + t];
    } else if (bid < 21504) {             /* wg concat */
        int n = bid - 20480;
        #pragma unroll
        for (int ii = 0; ii < 4; ii++) {
            int j = thr + 128*ii;
            owg[(long)n*512 + j] = (j < 256) ? Wih[(long)n*256 + j]
                                             : Whh[(long)n*256 + (j-256)];
        }
        if (thr == 0) obg[n] = bih[n] + bhh[n];
    } else {                              /* transpose x (B,C,K)->(B,K,C) */
        __shared__ float t[32][33];
        int idx = bid - 21504, b = idx >> 6, q = idx & 63;
        int k0 = (q & 15)*32, c0 = (q >> 4)*32;
        int tx = thr & 31, ty = thr >> 5;     /* ty 0..3 */
        const float* xb = x + (long)b*128*512;
        #pragma unroll
        for (int i = 0; i < 32; i += 4) t[ty+i][tx] = xb[(long)(c0+ty+i)*512 + k0+tx];
        __syncthreads();
        float* xo = oxt + (long)b*512*128;
        #pragma unroll
        for (int i = 0; i < 32; i += 4) xo[(long)(k0+ty+i)*128 + c0+tx] = t[tx][ty+i];
    }
}

/* ---------------- layernorm ---------------- */
__global__ __launch_bounds__(256) void ln_kernel(const float* __restrict__ in, int lda,
                                                 const float* __restrict__ g,
                                                 const float* __restrict__ bt,
                                                 float* __restrict__ out)
{
    int m = blockIdx.x*8 + (threadIdx.x >> 5);
    int lane = threadIdx.x & 31;
    float4 v = *(const float4*)(in + (long)m*lda + lane*4);
    float s = v.x+v.y+v.z+v.w, sq = v.x*v.x+v.y*v.y+v.z*v.z+v.w*v.w;
    #pragma unroll
    for (int o = 16; o; o >>= 1) {
        s  += __shfl_xor_sync(~0u, s,  o);
        sq += __shfl_xor_sync(~0u, sq, o);
    }
    float mu = s*(1.f/128.f), var = sq*(1.f/128.f) - mu*mu;
    float inv = rsqrtf(var + 1e-6f);
    float4 gg = *(const float4*)(g + lane*4), bb = *(const float4*)(bt + lane*4);
    float4 o4 = { (v.x-mu)*inv*gg.x+bb.x, (v.y-mu)*inv*gg.y+bb.y,
                  (v.z-mu)*inv*gg.z+bb.z, (v.w-mu)*inv*gg.w+bb.w };
    *(float4*)(out + (long)m*128 + lane*4) = o4;
}

/* ------- 128x128-tile f32x2 GEMM, double-buffered smem, occ 2 ------- */
__global__ __launch_bounds__(256,2) void gemm2(
    const float* __restrict__ A, int lda,
    const float* __restrict__ A2, int lda2, int splitK,
    const float* __restrict__ W, int ldw,
    const float* __restrict__ bias,
    const float* __restrict__ res, int ldr,
    float* __restrict__ C, int ldc,
    int Kd, int dil, int flags)
{
    __shared__ __align__(16) float As[2][TK][132], Ws[2][TK][132];
    const int m0 = blockIdx.x*128, n0 = blockIdx.y*128;
    const int tid = threadIdx.x;
    const int lrow = tid >> 2, ljj = (tid & 3)*4;
    const int tm = tid & 15, tn = tid >> 4;

    u64 acc[8][4];
    #pragma unroll
    for (int i = 0; i < 8; i++)
        #pragma unroll
        for (int j = 0; j < 4; j++) acc[i][j] = 0ull;

    auto fA = [&](int k0, int r) -> float4 {
        const float* src = A; int ld = lda; int kk = k0;
        if (splitK && k0 >= splitK) { src = A2; ld = lda2; kk = k0 - splitK; }
        int m = m0 + r;
        if (dil) {
            int t = k0 >> 7;
            m = (m & ~511) | ((m + (t-4)*dil) & 511);
            kk = k0 & 127;
        }
        return *(const float4*)(src + (long)m*ld + kk + ljj);
    };
    auto fW = [&](int k0, int r) -> float4 {
        return *(const float4*)(W + (long)(n0+r)*ldw + k0 + ljj);
    };

    float4 pa0 = fA(0, lrow), pa1 = fA(0, lrow+64);
    float4 pw0 = fW(0, lrow), pw1 = fW(0, lrow+64);

    auto stb = [&](int b, float4 a0, float4 a1, float4 w0, float4 w1) {
        As[b][ljj+0][lrow]=a0.x; As[b][ljj+1][lrow]=a0.y;
        As[b][ljj+2][lrow]=a0.z; As[b][ljj+3][lrow]=a0.w;
        As[b][ljj+0][lrow+64]=a1.x; As[b][ljj+1][lrow+64]=a1.y;
        As[b][ljj+2][lrow+64]=a1.z; As[b][ljj+3][lrow+64]=a1.w;
        Ws[b][ljj+0][lrow]=w0.x; Ws[b][ljj+1][lrow]=w0.y;
        Ws[b][ljj+2][lrow]=w0.z; Ws[b][ljj+3][lrow]=w0.w;
        Ws[b][ljj+0][lrow+64]=w1.x; Ws[b][ljj+1][lrow+64]=w1.y;
        Ws[b][ljj+2][lrow+64]=w1.z; Ws[b][ljj+3][lrow+64]=w1.w;
    };

    stb(0, pa0, pa1, pw0, pw1);
    __syncthreads();

    const int nt = Kd / TK;
    for (int t = 0; t < nt; t++) {
        const int cur = t & 1;
        const bool more = (t + 1 < nt);
        if (more) {
            pa0 = fA((t+1)*TK, lrow); pa1 = fA((t+1)*TK, lrow+64);
            pw0 = fW((t+1)*TK, lrow); pw1 = fW((t+1)*TK, lrow+64);
        }
        #pragma unroll
        for (int kk = 0; kk < TK; kk++) {
            float4 a0 = *(const float4*)&As[cur][kk][tm*8];
            float4 a1 = *(const float4*)&As[cur][kk][tm*8+4];
            ulonglong2 b0 = *(const ulonglong2*)&Ws[cur][kk][tn*8];
            ulonglong2 b1 = *(const ulonglong2*)&Ws[cur][kk][tn*8+4];
            u64 ad[8];
            ad[0]=dup2(a0.x); ad[1]=dup2(a0.y); ad[2]=dup2(a0.z); ad[3]=dup2(a0.w);
            ad[4]=dup2(a1.x); ad[5]=dup2(a1.y); ad[6]=dup2(a1.z); ad[7]=dup2(a1.w);
            #pragma unroll
            for (int i = 0; i < 8; i++) {
                fma2(acc[i][0], ad[i], b0.x);
                fma2(acc[i][1], ad[i], b0.y);
                fma2(acc[i][2], ad[i], b1.x);
                fma2(acc[i][3], ad[i], b1.y);
            }
        }
        if (more) stb(cur ^ 1, pa0, pa1, pw0, pw1);
        __syncthreads();
    }

    #pragma unroll
    for (int i = 0; i < 8; i++) {
        int mm = m0 + tm*8 + i;
        float* Cr = C + (long)mm*ldc + n0 + tn*8;
        float o[8];
        #pragma unroll
        for (int jp = 0; jp < 4; jp++) {
            float2 f = unp2(acc[i][jp]);
            o[2*jp] = f.x; o[2*jp+1] = f.y;
        }
        #pragma unroll
        for (int j = 0; j < 8; j++) {
            float v = o[j];
            if (bias) v += bias[n0 + tn*8 + j];
            if (flags & RELUF) v = fmaxf(v, 0.f);
            if (flags & RESF)  v += res[(long)mm*ldr + n0 + tn*8 + j];
            o[j] = v;
        }
        float4 w0 = {o[0],o[1],o[2],o[3]}, w1 = {o[4],o[5],o[6],o[7]};
        *(float4*)Cr = w0; *(float4*)(Cr+4) = w1;
    }
}

/* ------- 64x64 GEMM for small-N (p2) ------- */
__global__ __launch_bounds__(256) void gemm_kernel(
    const float* __restrict__ A, int lda,
    const float* __restrict__ W, int ldw,
    const float* __restrict__ bias,
    float* __restrict__ C, int ldc, int Kd, int flags)
{
    __shared__ __align__(16) float As[16][68], Ws[16][68];
    const int m0 = blockIdx.x*64, n0 = blockIdx.y*64;
    const int tid = threadIdx.x;
    const int row = tid >> 2, jj = (tid & 3)*4;
    const int tm = tid & 15, tn = tid >> 4;
    float acc[4][4];
    #pragma unroll
    for (int i = 0; i < 4; i++)
        #pragma unroll
        for (int j = 0; j < 4; j++) acc[i][j] = 0.f;
    const float* Ap = A + (long)(m0+row)*lda + jj;
    const float* Wp = W + (long)(n0+row)*ldw + jj;
    for (int k0 = 0; k0 < Kd; k0 += 16) {
        float4 av = *(const float4*)(Ap + k0);
        float4 wv = *(const float4*)(Wp + k0);
        As[jj+0][row]=av.x; As[jj+1][row]=av.y; As[jj+2][row]=av.z; As[jj+3][row]=av.w;
        Ws[jj+0][row]=wv.x; Ws[jj+1][row]=wv.y; Ws[jj+2][row]=wv.z; Ws[jj+3][row]=wv.w;
        __syncthreads();
        #pragma unroll
        for (int kk = 0; kk < 16; kk++) {
            float4 a = *(const float4*)&As[kk][tm*4];
            float4 b = *(const float4*)&Ws[kk][tn*4];
            float ar[4]={a.x,a.y,a.z,a.w}, br[4]={b.x,b.y,b.z,b.w};
            #pragma unroll
            for (int i = 0; i < 4; i++)
                #pragma unroll
                for (int j = 0; j < 4; j++) acc[i][j] = fmaf(ar[i], br[j], acc[i][j]);
        }
        __syncthreads();
    }
    #pragma unroll
    for (int i = 0; i < 4; i++) {
        int mm = m0 + tm*4 + i;
        float* Cr = C + (long)mm*ldc + n0 + tn*4;
        #pragma unroll
        for (int j = 0; j < 4; j++) {
            float v = acc[i][j];
            if (bias) v += bias[n0 + tn*4 + j];
            if (flags & RELUF) v = fmaxf(v, 0.f);
            Cr[j] = v;
        }
    }
}

/* ------- fused attention, block = (b, head, 64-query tile), f32x2 packed ------- */
#define ATTN_SMEM ((512*40 + 64*40 + 64*513)*4)
__global__ __launch_bounds__(256) void attn_kernel(const float* __restrict__ qkv,
                                                   float* __restrict__ r)
{
    extern __shared__ __align__(16) float sm[];
    float* ks = sm;
    float* qs = sm + 512*40;
    float* sc = sm + 512*40 + 64*40;
    const int qt = blockIdx.x, h = blockIdx.y, b = blockIdx.z;
    const int tid = threadIdx.x;
    const float* base = qkv + (long)b*512*768;

    for (int idx = tid; idx < 512*8; idx += 256) {
        int row = idx >> 3, j = idx & 7;
        *(float4*)&ks[row*40 + j*4] =
            *(const float4*)(base + (long)row*768 + 128 + h*32 + j*4);
    }
    for (int idx = tid; idx < 64*8; idx += 256) {
        int row = idx >> 3, j = idx & 7;
        *(float4*)&qs[row*40 + j*4] =
            *(const float4*)(base + (long)(qt*64+row)*768 + h*32 + j*4);
    }
    __syncthreads();
    {   /* scores */
        const int q = tid & 63, kc = tid >> 6;
        ulonglong2 qv[4], qv2[4];
        #pragma unroll
        for (int i = 0; i < 4; i++) {
            qv[i]  = *(const ulonglong2*)&qs[q*40 + i*8];
            qv2[i] = *(const ulonglong2*)&qs[q*40 + i*8 + 4];
        }
        for (int k = kc*128; k < kc*128 + 128; k++) {
            u64 a0=0ull, a1=0ull, a2=0ull, a3=0ull;
            #pragma unroll
            for (int i = 0; i < 4; i++) {
                ulonglong2 kv0 = *(const ulonglong2*)&ks[k*40 + i*8];
                ulonglong2 kv1 = *(const ulonglong2*)&ks[k*40 + i*8 + 4];
                fma2(a0, qv[i].x,  kv0.x);
                fma2(a1, qv[i].y,  kv0.y);
                fma2(a2, qv2[i].x, kv1.x);
                fma2(a3, qv2[i].y, kv1.y);
            }
            add2(a0, a2); add2(a1, a3); add2(a0, a1);
            float2 f = unp2(a0);
            sc[q*513 + k] = f.x + f.y;
        }
    }
    __syncthreads();
    {   /* softmax */
        const int warp = tid >> 5, lane = tid & 31;
        const float scale = 0.17677669529663689f;
        for (int row = warp; row < 64; row += 8) {
            float* sr = sc + row*513;
            float mx = -1e30f;
            for (int i = lane; i < 512; i += 32) mx = fmaxf(mx, sr[i]);
            #pragma unroll
            for (int o = 16; o; o >>= 1) mx = fmaxf(mx, __shfl_xor_sync(~0u, mx, o));
            float sum = 0.f;
            for (int i = lane; i < 512; i += 32) {
                float e = __expf((sr[i] - mx)*scale);
                sr[i] = e; sum += e;
            }
            #pragma unroll
            for (int o = 16; o; o >>= 1) sum += __shfl_xor_sync(~0u, sum, o);
            float inv = 1.f / sum;
            for (int i = lane; i < 512; i += 32) sr[i] *= inv;
        }
    }
    /* AV: V streamed in 4 chunks of 128 keys */
    const int qg = tid >> 4, cg = tid & 15;
    u64 acc[4][4];
    #pragma unroll
    for (int i = 0; i < 4; i++)
        #pragma unroll
        for (int j = 0; j < 4; j++) acc[i][j] = 0ull;
    for (int kc = 0; kc < 4; kc++) {
        __syncthreads();
        for (int idx = tid; idx < 128*32; idx += 256) {
            int row = idx >> 5, j = idx & 31;
            *(float4*)&ks[row*136 + j*4] =
                *(const float4*)(base + (long)(kc*128+row)*768 + 256 + h*128 + j*4);
        }
        __syncthreads();
        for (int k = 0; k < 128; k++) {
            ulonglong2 v0 = *(const ulonglong2*)&ks[k*136 + cg*8];
            ulonglong2 v1 = *(const ulonglong2*)&ks[k*136 + cg*8 + 4];
            int kk = kc*128 + k;
            #pragma unroll
            for (int qq = 0; qq < 4; qq++) {
                u64 pd = dup2(sc[(qg*4+qq)*513 + kk]);
                fma2(acc[qq][0], pd, v0.x);
                fma2(acc[qq][1], pd, v0.y);
                fma2(acc[qq][2], pd, v1.x);
                fma2(acc[qq][3], pd, v1.y);
            }
        }
    }
    #pragma unroll
    for (int qq = 0; qq < 4; qq++) {
        float* rp = r + ((long)(b*512 + qt*64 + qg*4 + qq))*512 + h*128 + cg*8;
        float2 c0 = unp2(acc[qq][0]), c1 = unp2(acc[qq][1]);
        float2 c2 = unp2(acc[qq][2]), c3 = unp2(acc[qq][3]);
        float4 w0 = {c0.x,c0.y,c1.x,c1.y}, w1 = {c2.x,c2.y,c3.x,c3.y};
        *(float4*)rp = w0; *(float4*)(rp+4) = w1;
    }
}

/* ------- fus max over K + broadcast ------- */
__global__ void maxg_kernel(const float* __restrict__ fus, float* __restrict__ feat)
{
    int b = blockIdx.x, o = threadIdx.x;
    float m = -1e30f;
    for (int k = 0; k < 512; k++)
        m = fmaxf(m, fus[((long)b*512 + k)*256 + o]);
    for (int k = 0; k < 512; k++)
        feat[((long)b*512 + k)*1536 + 256 + o] = m;
}

__device__ __forceinline__ float sigf(float x) { return 1.f/(1.f + __expf(-x)); }

__global__ void lstm_kernel(const float* __restrict__ g, const float* __restrict__ c0,
                            float* __restrict__ feat, float* __restrict__ oh,
                            float* __restrict__ oc)
{
    long row = blockIdx.x; int j = threadIdx.x;
    const float* gr = g + row*1024;
    float gi = gr[j], gf = gr[256+j], gg = gr[512+j], go = gr[768+j];
    float c = sigf(gf)*c0[row*256 + j] + sigf(gi)*tanhf(gg);
    float hh = sigf(go)*tanhf(c);
    oh[row*256 + j] = hh;
    oc[row*256 + j] = c;
    feat[row*1536 + j] = hh;
}

__global__ void p3_kernel(const float* __restrict__ p2, const float* __restrict__ w,
                          const float* __restrict__ bias, float* __restrict__ out)
{
    __shared__ float ws[128];
    int b = blockIdx.x, k = threadIdx.x;
    if (k < 128) ws[k] = w[k];
    __syncthreads();
    const float* pr = p2 + (long)(b*512 + k)*64;
    float s0 = bias[0], s1 = bias[1];
    for (int c = 0; c < 64; c++) {
        float v = pr[c];
        s0 = fmaf(v, ws[c], s0);
        s1 = fmaf(v, ws[64+c], s1);
    }
    out[(long)b*1024 + k]       = s0;
    out[(long)b*1024 + 512 + k] = s1;
}

static const int DILS[8] = {1,1,1,1,2,2,4,4};

extern "C" void kernel_launch(void* const* d_in, const int* in_sizes, int n_in,
                              void* d_out, int out_size)
{
    const float *x=(const float*)d_in[0], *h0=(const float*)d_in[1], *c0=(const float*)d_in[2];
    const float *ln_g=(const float*)d_in[3], *ln_b=(const float*)d_in[4];
    const float *Wq=(const float*)d_in[5], *Wk=(const float*)d_in[6], *Wv=(const float*)d_in[7];
    const float *Ww=(const float*)d_in[8], *Wa=(const float*)d_in[9];
    const float *cw=(const float*)d_in[10], *cb=(const float*)d_in[11];
    const float *fus_w=(const float*)d_in[12], *fus_b=(const float*)d_in[13];
    const float *rs_w=(const float*)d_in[14], *rs_b=(const float*)d_in[15];
    const float *W_ih=(const float*)d_in[16], *W_hh=(const float*)d_in[17];
    const float *b_ih=(const float*)d_in[18], *b_hh=(const float*)d_in[19];
    const float *p1_w=(const float*)d_in[20], *p1_b=(const float*)d_in[21];
    const float *p2_w=(const float*)d_in[22], *p2_b=(const float*)d_in[23];
    const float *p3_w=(const float*)d_in[24], *p3_b=(const float*)d_in[25];
    float* out = (float*)d_out;

    float* buf; cudaGetSymbolAddress((void**)&buf, BUF);
    float *LN=buf+O_LN, *QKV=buf+O_QKV, *R=buf+O_R, *TMP=buf+O_TMP, *XT=buf+O_XT;
    float *FEAT=buf+O_FEAT, *FUS=buf+O_FUS, *GATES=buf+O_GATES, *P1=buf+O_P1, *P2=buf+O_P2;
    float *WQKV=buf+O_WQKV, *WCONV=buf+O_WCONV, *WCB=buf+O_WCB, *WG=buf+O_WG, *BG=buf+O_BG;

    cudaFuncSetAttribute(attn_kernel, cudaFuncAttributeMaxDynamicSharedMemorySize, ATTN_SMEM);

    /* launch 0: all weight prep + input transpose */
    prep_all<<<25600,128>>>(Wq, Wk, Wv, Ww, Wa, cw, W_ih, W_hh, b_ih, b_hh, x,
                            WQKV, WCB, WCONV, WG, BG, XT);

    for (int i = 0; i < 8; i++) {
        const float* in = (i == 0) ? XT : FEAT + 512 + 128*(i-1);
        int ldin = (i == 0) ? 128 : 1536;
        float* hout = FEAT + 512 + 128*i;
        ln_kernel<<<4096,256>>>(in, ldin, ln_g + i*128, ln_b + i*128, LN);
        gemm2<<<dim3(256,6),256>>>(LN,128, nullptr,0,0, WQKV+(long)i*98304,128,
                                   nullptr, nullptr,0, QKV,768, 128, 0, 0);
        attn_kernel<<<dim3(8,4,64),256,ATTN_SMEM>>>(QKV, R);
        /* TMP = R @ Wc + in @ Wab  (split-K) */
        gemm2<<<dim3(256,1),256>>>(R,512, in,ldin,512, WCB+(long)i*81920,640,
                                   nullptr, nullptr,0, TMP,128, 640, 0, 0);
        /* conv: single GEMM K=1152 with per-tap circular shift (launch #5 for i=0) */
        int flags = RELUF; const float* res = nullptr;
        if (i > 0) { flags |= RESF; res = FEAT + 512 + 128*(i-1); }
        gemm2<<<dim3(256,1),256>>>(TMP,128, nullptr,0,0, WCONV+(long)i*147456,1152,
                                   cb + i*128, res,1536, hout,1536, 1152, DILS[i], flags);
    }
    /* tail */
    gemm2<<<dim3(256,2),256>>>(FEAT+512,1536, nullptr,0,0, fus_w,1024, fus_b,
                               nullptr,0, FUS,256, 1024, 0, 0);
    maxg_kernel<<<64,256>>>(FUS, FEAT);
    gemm2<<<dim3(256,2),256>>>(FEAT+256,1536, nullptr,0,0, rs_w,1280, rs_b,
                               nullptr,0, QKV,256, 1280, 0, 0);
    gemm2<<<dim3(256,8),256>>>(QKV,256, h0,256,256, WG,512, BG,
                               nullptr,0, GATES,1024, 512, 0, 0);
    lstm_kernel<<<32768,256>>>(GATES, c0, FEAT, out + 65536, out + 65536 + 8388608);
    gemm2<<<dim3(256,2),256>>>(FEAT,1536, nullptr,0,0, p1_w,1536, p1_b,
                               nullptr,0, P1,256, 1536, 0, RELUF);
    gemm_kernel<<<dim3(512,1),256>>>(P1,256, p2_w,256, p2_b, P2,64, 256, RELUF);
    p3_kernel<<<64,512>>>(P2, p3_w, p3_b, out);
}